// round 16
// baseline (speedup 1.0000x reference)
#include <cuda_runtime.h>
#include <cuda_fp16.h>
#include <mma.h>
#include <math.h>

using namespace nvcuda;

#define B_   2
#define S_   2048
#define D_   1024
#define H_   16
#define DC_  64
#define HC_  16
#define MFF_ 4096
#define DH_  64
#define BS_  (B_*S_)      // 4096
#define BH_  (B_*H_)      // 32

// ---------------- scratch (static device globals; no allocation) ----------------
__device__ float  g_zh  [BS_*H_*HC_];
__device__ float  g_h1  [BS_*D_];
__device__ float  g_ztmp[BS_*DC_];
__device__ float  g_zsq [BS_*H_];
// half activations / operands
__device__ __half g_hn_h  [BS_*D_];
__device__ __half g_val_h [BS_*D_];
__device__ __half g_attn_h[BS_*D_];
__device__ __half g_hn2_h [BS_*D_];
__device__ __half g_mid_h [BS_*MFF_];
__device__ __half g_zhi   [BS_*H_*HC_];  // hi part of zh (Dekker split)
__device__ __half g_zlo   [BS_*H_*HC_];  // lo part
// half weight copies
__device__ __half g_wv_h [D_*D_];
__device__ __half g_wca_h[DC_*H_*HC_];
__device__ __half g_wcn_h[D_*DC_];
__device__ __half g_wo_h [D_*D_];
__device__ __half g_w1_h [D_*MFF_];
__device__ __half g_w2_h [MFF_*D_];
__device__ __half g_z_h  [BS_*DC_];

// exp(s) for s <= 0, FMA-pipe only (no MUFU). ~2.4e-6 max rel err.
__device__ __forceinline__ float fast_exp_neg(float s) {
    float y = fmaxf(s * 1.4426950408889634f, -126.0f);
    float z = y + 12582912.0f;
    float r = z - 12582912.0f;
    float f = y - r;
    int   iz = __float_as_int(z);
    float sc = __int_as_float((iz + (127 - 0x400000)) << 23);
    float p = 0.0013333558f;
    p = fmaf(p, f, 0.0096181291f);
    p = fmaf(p, f, 0.0555041087f);
    p = fmaf(p, f, 0.2402265070f);
    p = fmaf(p, f, 0.6931471806f);
    p = fmaf(p, f, 1.0f);
    return sc * p;
}

enum { EPI_BIAS_F32 = 0, EPI_RES_F32 = 1, EPI_GELU_H = 2, EPI_BIAS_H = 3 };

__device__ __forceinline__ void cp_async16(void* smem_dst, const void* gmem_src) {
    unsigned sa = (unsigned)__cvta_generic_to_shared(smem_dst);
    asm volatile("cp.async.cg.shared.global [%0], [%1], 16;\n" :: "r"(sa), "l"(gmem_src));
}
__device__ __forceinline__ void cp_async4(void* smem_dst, const void* gmem_src) {
    unsigned sa = (unsigned)__cvta_generic_to_shared(smem_dst);
    asm volatile("cp.async.ca.shared.global [%0], [%1], 4;\n" :: "r"(sa), "l"(gmem_src));
}
__device__ __forceinline__ void cp_commit() {
    asm volatile("cp.async.commit_group;\n" ::);
}

// ---------------- fp32 -> fp16 conversion (float4 -> 4 halves) ----------------
__global__ void f2h_kernel(const float* __restrict__ x, __half* __restrict__ y, int n4) {
    int i = blockIdx.x * blockDim.x + threadIdx.x;
    if (i < n4) {
        float4 v = ((const float4*)x)[i];
        __half2* yp = (__half2*)y;
        yp[2*i]   = __floats2half2_rn(v.x, v.y);
        yp[2*i+1] = __floats2half2_rn(v.z, v.w);
    }
}

// ---------------- score prep: Dekker split zh -> (hi, lo) fp16 + per-head norms --
__global__ void score_prep(const float* __restrict__ zh, __half* __restrict__ hi,
                           __half* __restrict__ lo, float* __restrict__ zsq)
{
    int t = blockIdx.x * blockDim.x + threadIdx.x;
    if (t >= BS_ * H_) return;
    const float4* src = (const float4*)(zh + (size_t)t * 16);
    __half hb[16], lb[16];
    float s = 0.f;
#pragma unroll
    for (int q = 0; q < 4; q++) {
        float4 v = src[q];
        float vv[4] = {v.x, v.y, v.z, v.w};
#pragma unroll
        for (int j = 0; j < 4; j++) {
            float x = vv[j];
            __half hx = __float2half_rn(x);
            float  rx = x - __half2float(hx);
            hb[q*4+j] = hx;
            lb[q*4+j] = __float2half_rn(rx);
            s = fmaf(x, x, s);
        }
    }
    ((uint4*)(hi + (size_t)t * 16))[0] = ((uint4*)hb)[0];
    ((uint4*)(hi + (size_t)t * 16))[1] = ((uint4*)hb)[1];
    ((uint4*)(lo + (size_t)t * 16))[0] = ((uint4*)lb)[0];
    ((uint4*)(lo + (size_t)t * 16))[1] = ((uint4*)lb)[1];
    zsq[t] = s;
}

// ---------------- fused flash attention (all tensor-core) ----------------------
// Per CTA: 128 q-rows of one (b,h). 16 k-tiles of 128.
// K/V/ksq are double-buffered and cp.async-prefetched ONE FULL TILE ahead:
// exactly one outstanding commit-group at each wait -> wait_group(0).
// smem (bytes):
//  qh 0 (6144), ql 6144, kh 12288 (2x6144), kl 24576 (2x6144),
//  qsq 36864 (512), ksq 37376 (2x512), C 38400 (34816),
//  Ph 73216 (34816), Vs 108032 (2x18432)  => total 144896
#define AT_QH   0
#define AT_QL   6144
#define AT_KH   12288
#define AT_KL   24576
#define AT_QSQ  36864
#define AT_KSQ  37376
#define AT_C    38400
#define AT_PH   73216
#define AT_VS   108032
#define AT_SMEM 144896

__global__ void __launch_bounds__(256, 1) attn_mma(
    const __half* __restrict__ zhi, const __half* __restrict__ zlo,
    const float* __restrict__ zsq, const float* __restrict__ gamma,
    const __half* __restrict__ V, __half* __restrict__ O)
{
    constexpr int LDQ = 24;   // halves
    constexpr int LDC = 68;   // floats
    constexpr int LDP = 136;  // halves
    constexpr int LDV = 72;   // halves
    constexpr int KBUF = 128 * LDQ;    // halves per K buffer
    constexpr int VBUF = 128 * LDV;    // halves per V buffer
    extern __shared__ __align__(16) char smraw[];
    __half* qh  = (__half*)(smraw + AT_QH);
    __half* ql  = (__half*)(smraw + AT_QL);
    __half* kh  = (__half*)(smraw + AT_KH);
    __half* kl  = (__half*)(smraw + AT_KL);
    float*  qsq = (float*)(smraw + AT_QSQ);
    float*  ksq = (float*)(smraw + AT_KSQ);
    float*  C   = (float*)(smraw + AT_C);
    __half* Ph  = (__half*)(smraw + AT_PH);
    __half* Vs  = (__half*)(smraw + AT_VS);

    const int tid = threadIdx.x;
    const int wid = tid >> 5;
    const int bh = blockIdx.y;
    const int b = bh >> 4, h = bh & 15;
    const int q0 = blockIdx.x * 128;

    const float gx = gamma[h];
    const float g = (gx > 20.f) ? gx : log1pf(__expf(gx));
    const __half* Vb = V + (size_t)b * S_ * D_ + h * DH_;

    // q tiles (hi/lo) + norms (direct loads; one-time)
    {
        int r = tid >> 1, part = tid & 1;
        size_t go = ((size_t)(b * S_ + q0 + r)) * (H_ * HC_) + h * 16 + part * 8;
        *(uint4*)(qh + r * LDQ + part * 8) = *(const uint4*)(zhi + go);
        *(uint4*)(ql + r * LDQ + part * 8) = *(const uint4*)(zlo + go);
        if (part == 0) qsq[r] = zsq[(size_t)(b * S_ + q0 + r) * H_ + h];
    }

    // prefetch of K/V/ksq for tile kt into buffer kt&1
    auto prefetch = [&](int kt) {
        const int k0 = kt * 128;
        const int buf = kt & 1;
        __half* khd = kh + buf * KBUF;
        __half* kld = kl + buf * KBUF;
        {
            int r = tid >> 1, part = tid & 1;
            size_t go = ((size_t)(b * S_ + k0 + r)) * (H_ * HC_) + h * 16 + part * 8;
            cp_async16(khd + r * LDQ + part * 8, zhi + go);
            cp_async16(kld + r * LDQ + part * 8, zlo + go);
        }
        if (tid < 128)
            cp_async4(ksq + buf * 128 + tid, zsq + (size_t)(b * S_ + k0 + tid) * H_ + h);
        __half* Vd = Vs + buf * VBUF;
#pragma unroll
        for (int i = tid; i < 128 * 8; i += 256) {
            int r = i >> 3, c = (i & 7) * 8;
            cp_async16(Vd + r * LDV + c, Vb + (size_t)(k0 + r) * D_ + c);
        }
    };

    prefetch(0);
    cp_commit();
    __syncthreads();   // q tiles visible

    wmma::fragment<wmma::matrix_a, 16, 16, 16, __half, wmma::row_major> a_hi, a_lo;
    wmma::load_matrix_sync(a_hi, qh + (wid * 16) * LDQ, LDQ);
    wmma::load_matrix_sync(a_lo, ql + (wid * 16) * LDQ, LDQ);

    const int row = tid >> 1;
    const int c0  = (tid & 1) * 32;
    const float qs = qsq[row];
    float rs = 0.f;

    wmma::fragment<wmma::accumulator, 16, 16, 16, float> acc_o[4];
#pragma unroll
    for (int j = 0; j < 4; j++) wmma::fill_fragment(acc_o[j], 0.0f);

    for (int kt = 0; kt < 16; ++kt) {
        const int buf = kt & 1;
        asm volatile("cp.async.wait_group 0;\n" ::);   // tile kt's group (only one outstanding)
        __syncthreads();   // data visible to all; all warps done with buf^1 from tile kt-1
        if (kt + 1 < 16) { prefetch(kt + 1); cp_commit(); }

        const __half* khb = kh + buf * KBUF;
        const __half* klb = kl + buf * KBUF;
        const float*  ksb = ksq + buf * 128;

        // ---- score MMAs: warp wid -> q rows wid*16..+15 x all 128 k cols
        wmma::fragment<wmma::accumulator, 16, 16, 16, float> acc[8];
#pragma unroll
        for (int j = 0; j < 8; j++) wmma::fill_fragment(acc[j], 0.0f);
#pragma unroll
        for (int j = 0; j < 8; j++) {
            wmma::fragment<wmma::matrix_b, 16, 16, 16, __half, wmma::col_major> b_hi, b_lo;
            wmma::load_matrix_sync(b_hi, khb + (j * 16) * LDQ, LDQ);
            wmma::load_matrix_sync(b_lo, klb + (j * 16) * LDQ, LDQ);
            wmma::mma_sync(acc[j], a_hi, b_hi, acc[j]);
            wmma::mma_sync(acc[j], a_hi, b_lo, acc[j]);
            wmma::mma_sync(acc[j], a_lo, b_hi, acc[j]);
        }

        // ---- exp epilogue into SMEM Ph, two 64-col halves via C buffer
#pragma unroll
        for (int hv = 0; hv < 2; ++hv) {
#pragma unroll
            for (int jj = 0; jj < 4; jj++)
                wmma::store_matrix_sync(C + (wid * 16) * LDC + jj * 16,
                                        acc[hv * 4 + jj], LDC, wmma::mem_row_major);
            __syncthreads();
            const float* Crow = C + row * LDC + c0;
            const float* ks   = ksb + hv * 64 + c0;
            __half hb[32];
#pragma unroll
            for (int i = 0; i < 32; i += 4) {
                float4 dv = *(const float4*)(Crow + i);
                float d0 = fmaxf(fmaf(-2.f, dv.x, qs + ks[i + 0]), 0.f);
                float d1 = fmaxf(fmaf(-2.f, dv.y, qs + ks[i + 1]), 0.f);
                float d2 = fmaxf(fmaf(-2.f, dv.z, qs + ks[i + 2]), 0.f);
                float d3 = fmaxf(fmaf(-2.f, dv.w, qs + ks[i + 3]), 0.f);
                float p0 = fast_exp_neg(-g * d0);
                float p1 = fast_exp_neg(-g * d1);
                float p2 = fast_exp_neg(-g * d2);
                float p3 = fast_exp_neg(-g * d3);
                rs += (p0 + p1) + (p2 + p3);
                *(__half2*)&hb[i]     = __floats2half2_rn(p0, p1);
                *(__half2*)&hb[i + 2] = __floats2half2_rn(p2, p3);
            }
            __half* Pp = Ph + (size_t)row * LDP + hv * 64 + c0;
#pragma unroll
            for (int i = 0; i < 4; i++) ((uint4*)Pp)[i] = ((uint4*)hb)[i];
            __syncthreads();
        }

        // ---- PV: O += P(128x128) @ V(128x64); V already resident (prefetched)
        const __half* Vsb = Vs + buf * VBUF;
#pragma unroll
        for (int kk = 0; kk < 128; kk += 16) {
            wmma::fragment<wmma::matrix_a, 16, 16, 16, __half, wmma::row_major> af;
            wmma::load_matrix_sync(af, Ph + (wid * 16) * LDP + kk, LDP);
#pragma unroll
            for (int j = 0; j < 4; j++) {
                wmma::fragment<wmma::matrix_b, 16, 16, 16, __half, wmma::row_major> bf;
                wmma::load_matrix_sync(bf, Vsb + kk * LDV + j * 16, LDV);
                wmma::mma_sync(acc_o[j], af, bf, acc_o[j]);
            }
        }
    }

    rs += __shfl_xor_sync(0xffffffffu, rs, 1);
    __syncthreads();               // all PV reads of Ph/C done
    if ((tid & 1) == 0) qsq[row] = 1.0f / rs;   // qsq reused as linv
#pragma unroll
    for (int j = 0; j < 4; j++)
        wmma::store_matrix_sync(C + (wid * 16) * LDC + j * 16, acc_o[j], LDC, wmma::mem_row_major);
    __syncthreads();

#pragma unroll 4
    for (int i = tid; i < 128 * 16; i += 256) {
        int r = i >> 4, c = (i & 15) * 4;
        float4 v = *(float4*)&C[r * LDC + c];
        float li = qsq[r];
        v.x *= li; v.y *= li; v.z *= li; v.w *= li;
        __half2* yp = (__half2*)(O + ((size_t)(b * S_ + q0 + r)) * D_ + h * DH_ + c);
        yp[0] = __floats2half2_rn(v.x, v.y);
        yp[1] = __floats2half2_rn(v.z, v.w);
    }
}

// ---------------- pipelined fp16 GEMM: C = epi(A[M,K] @ B[K,N] + bias) ----------------
// R14-proven config: BK=32, 3 stages, wait_group(1).
template<int BM, int BN, int EPI>
__global__ void __launch_bounds__(128, 2) gemm_h(
    const __half* __restrict__ A, const __half* __restrict__ Bw,
    const float* __restrict__ bias, const float* __restrict__ Rres,
    void* __restrict__ Cout, int Mdim, int Ndim, int Kdim)
{
    constexpr int BK = 32;
    constexpr int STAGES = 3;
    constexpr int LDA = BK + 8;
    constexpr int LDB = BN + 8;
    constexpr int LDC = BN + 4;
    constexpr int WTM = BM / 2;
    constexpr int WTN = BN / 2;
    constexpr int FM  = WTM / 16;
    constexpr int FN  = WTN / 16;
    constexpr int A_STG = BM * LDA;
    constexpr int B_STG = BK * LDB;
    constexpr int CHB = BN / 8;

    extern __shared__ __align__(16) char smraw[];
    __half* As = (__half*)smraw;
    __half* Bs = As + STAGES * A_STG;

    const int tid = threadIdx.x;
    const int wid = tid >> 5;
    const int wm = wid >> 1, wn = wid & 1;
    const int bm0 = blockIdx.y * BM, bn0 = blockIdx.x * BN;

    wmma::fragment<wmma::accumulator, 16, 16, 16, float> acc[FM][FN];
#pragma unroll
    for (int i = 0; i < FM; i++)
#pragma unroll
        for (int j = 0; j < FN; j++) wmma::fill_fragment(acc[i][j], 0.0f);

    auto load_tile = [&](int stage, int k0) {
        __half* Ad = As + stage * A_STG;
        __half* Bd = Bs + stage * B_STG;
#pragma unroll
        for (int i = tid; i < BM * 4; i += 128) {
            int r = i >> 2, c = (i & 3) * 8;
            cp_async16(Ad + r * LDA + c, A + (size_t)(bm0 + r) * Kdim + k0 + c);
        }
#pragma unroll
        for (int i = tid; i < BK * CHB; i += 128) {
            int r = i / CHB, c = (i % CHB) * 8;
            cp_async16(Bd + r * LDB + c, Bw + (size_t)(k0 + r) * Ndim + bn0 + c);
        }
    };

    const int KT = Kdim / BK;
#pragma unroll
    for (int s = 0; s < STAGES - 1; ++s) {
        if (s < KT) load_tile(s, s * BK);
        cp_commit();
    }

    int read = 0, write = STAGES - 1;
    for (int it = 0; it < KT; ++it) {
        asm volatile("cp.async.wait_group %0;\n" :: "n"(STAGES - 2));
        __syncthreads();
        int knext = (it + STAGES - 1) * BK;
        if (knext < Kdim) load_tile(write, knext);
        cp_commit();

        const __half* Asr = As + read * A_STG;
        const __half* Bsr = Bs + read * B_STG;
#pragma unroll
        for (int kk = 0; kk < BK; kk += 16) {
            wmma::fragment<wmma::matrix_a, 16, 16, 16, __half, wmma::row_major> af[FM];
            wmma::fragment<wmma::matrix_b, 16, 16, 16, __half, wmma::row_major> bf[FN];
#pragma unroll
            for (int i = 0; i < FM; i++)
                wmma::load_matrix_sync(af[i], Asr + (wm * WTM + i * 16) * LDA + kk, LDA);
#pragma unroll
            for (int j = 0; j < FN; j++)
                wmma::load_matrix_sync(bf[j], Bsr + kk * LDB + wn * WTN + j * 16, LDB);
#pragma unroll
            for (int i = 0; i < FM; i++)
#pragma unroll
                for (int j = 0; j < FN; j++)
                    wmma::mma_sync(acc[i][j], af[i], bf[j], acc[i][j]);
        }
        read = (read + 1) % STAGES;
        write = (write + 1) % STAGES;
    }

    asm volatile("cp.async.wait_group 0;\n" ::);
    __syncthreads();

    float* Cs = (float*)smraw;
#pragma unroll
    for (int i = 0; i < FM; i++)
#pragma unroll
        for (int j = 0; j < FN; j++)
            wmma::store_matrix_sync(Cs + (wm * WTM + i * 16) * LDC + wn * WTN + j * 16,
                                    acc[i][j], LDC, wmma::mem_row_major);
    __syncthreads();

#pragma unroll 4
    for (int i = tid; i < BM * (BN / 4); i += 128) {
        int r = i / (BN / 4), c = (i % (BN / 4)) * 4;
        float4 v = *(float4*)&Cs[r * LDC + c];
        float4 bb = *(const float4*)(bias + bn0 + c);
        v.x += bb.x; v.y += bb.y; v.z += bb.z; v.w += bb.w;
        size_t off = (size_t)(bm0 + r) * Ndim + bn0 + c;
        if (EPI == EPI_BIAS_F32) {
            *(float4*)((float*)Cout + off) = v;
        } else if (EPI == EPI_RES_F32) {
            float4 rr = *(const float4*)(Rres + off);
            v.x += rr.x; v.y += rr.y; v.z += rr.z; v.w += rr.w;
            *(float4*)((float*)Cout + off) = v;
        } else if (EPI == EPI_GELU_H) {
            v.x = 0.5f * v.x * (1.0f + erff(v.x * 0.70710678118654752f));
            v.y = 0.5f * v.y * (1.0f + erff(v.y * 0.70710678118654752f));
            v.z = 0.5f * v.z * (1.0f + erff(v.z * 0.70710678118654752f));
            v.w = 0.5f * v.w * (1.0f + erff(v.w * 0.70710678118654752f));
            __half2* yp = (__half2*)((__half*)Cout + off);
            yp[0] = __floats2half2_rn(v.x, v.y);
            yp[1] = __floats2half2_rn(v.z, v.w);
        } else {
            __half2* yp = (__half2*)((__half*)Cout + off);
            yp[0] = __floats2half2_rn(v.x, v.y);
            yp[1] = __floats2half2_rn(v.z, v.w);
        }
    }
}

// ---------------- LayerNorm D=1024, vectorized (fp32 or fp16 output) -----------
template<bool HOUT>
__global__ void ln1024(const float* __restrict__ x, const float* __restrict__ gm,
                       const float* __restrict__ bt, void* __restrict__ y)
{
    const int row = blockIdx.x;
    const int tid = threadIdx.x;
    float4 v = ((const float4*)x)[(size_t)row * 256 + tid];
    float s  = (v.x + v.y) + (v.z + v.w);
    float s2 = fmaf(v.x, v.x, fmaf(v.y, v.y, fmaf(v.z, v.z, v.w * v.w)));
    __shared__ float red[2][8];
    const int lane = tid & 31, wid = tid >> 5;
#pragma unroll
    for (int off = 16; off; off >>= 1) {
        s  += __shfl_xor_sync(0xffffffffu, s, off);
        s2 += __shfl_xor_sync(0xffffffffu, s2, off);
    }
    if (lane == 0) { red[0][wid] = s; red[1][wid] = s2; }
    __syncthreads();
    if (wid == 0) {
        s  = (lane < 8) ? red[0][lane] : 0.f;
        s2 = (lane < 8) ? red[1][lane] : 0.f;
#pragma unroll
        for (int off = 4; off; off >>= 1) {
            s  += __shfl_xor_sync(0xffffffffu, s, off);
            s2 += __shfl_xor_sync(0xffffffffu, s2, off);
        }
        if (lane == 0) { red[0][0] = s; red[1][0] = s2; }
    }
    __syncthreads();
    s = red[0][0]; s2 = red[1][0];
    const float mean = s * (1.0f / 1024.0f);
    const float var  = s2 * (1.0f / 1024.0f) - mean * mean;
    const float inv  = rsqrtf(var + 1e-5f);
    float4 g4 = ((const float4*)gm)[tid];
    float4 b4 = ((const float4*)bt)[tid];
    float4 o;
    o.x = (v.x - mean) * inv * g4.x + b4.x;
    o.y = (v.y - mean) * inv * g4.y + b4.y;
    o.z = (v.z - mean) * inv * g4.z + b4.z;
    o.w = (v.w - mean) * inv * g4.w + b4.w;
    if (HOUT) {
        __half2* yp = (__half2*)((__half*)y + (size_t)row * 1024 + tid * 4);
        yp[0] = __floats2half2_rn(o.x, o.y);
        yp[1] = __floats2half2_rn(o.z, o.w);
    } else {
        ((float4*)y)[(size_t)row * 256 + tid] = o;
    }
}

// ---------------- generic LayerNorm (small Dd) ----------------
__global__ void ln_small(const float* __restrict__ x, const float* __restrict__ gm,
                         const float* __restrict__ bt, float* __restrict__ y, int Dd)
{
    const int row = blockIdx.x;
    const float* xr = x + (size_t)row * Dd;
    float s = 0.f, s2 = 0.f;
    for (int i = threadIdx.x; i < Dd; i += blockDim.x) {
        float v = xr[i]; s += v; s2 = fmaf(v, v, s2);
    }
#pragma unroll
    for (int off = 16; off; off >>= 1) {
        s  += __shfl_xor_sync(0xffffffffu, s, off);
        s2 += __shfl_xor_sync(0xffffffffu, s2, off);
    }
    s  = __shfl_sync(0xffffffffu, s, 0);
    s2 = __shfl_sync(0xffffffffu, s2, 0);
    const float mean = s / Dd;
    const float var  = s2 / Dd - mean * mean;
    const float inv  = rsqrtf(var + 1e-5f);
    float* yr = y + (size_t)row * Dd;
    for (int i = threadIdx.x; i < Dd; i += blockDim.x)
        yr[i] = (xr[i] - mean) * inv * gm[i] + bt[i];
}

// ---------------- launch ----------------
extern "C" void kernel_launch(void* const* d_in, const int* in_sizes, int n_in,
                              void* d_out, int out_size)
{
    const float* h    = (const float*)d_in[0];
    const float* z    = (const float*)d_in[1];
    const float* wv   = (const float*)d_in[2];
    const float* bv   = (const float*)d_in[3];
    const float* wca  = (const float*)d_in[4];
    const float* bca  = (const float*)d_in[5];
    const float* wcn  = (const float*)d_in[6];
    const float* bcn  = (const float*)d_in[7];
    const float* wo   = (const float*)d_in[8];
    const float* bo   = (const float*)d_in[9];
    const float* gamma= (const float*)d_in[10];
    const float* w1   = (const float*)d_in[11];
    const float* b1   = (const float*)d_in[12];
    const float* w2   = (const float*)d_in[13];
    const float* b2   = (const float*)d_in[14];
    const float* ln1g = (const float*)d_in[15];
    const float* ln1b = (const float*)d_in[16];
    const float* ln2g = (const float*)d_in[17];
    const float* ln2b = (const float*)d_in[18];
    const float* lncg = (const float*)d_in[19];
    const float* lncb = (const float*)d_in[20];

    float* out_h = (float*)d_out;
    float* out_z = out_h + (size_t)BS_ * D_;

    float  *p_zh, *p_h1, *p_ztmp, *p_zsq;
    __half *p_hn, *p_val, *p_attn, *p_hn2, *p_mid, *p_zhi, *p_zlo;
    __half *p_wv, *p_wca, *p_wcn, *p_wo, *p_w1, *p_w2, *p_z;
    cudaGetSymbolAddress((void**)&p_zh,  g_zh);
    cudaGetSymbolAddress((void**)&p_h1,  g_h1);
    cudaGetSymbolAddress((void**)&p_ztmp,g_ztmp);
    cudaGetSymbolAddress((void**)&p_zsq, g_zsq);
    cudaGetSymbolAddress((void**)&p_hn,  g_hn_h);
    cudaGetSymbolAddress((void**)&p_val, g_val_h);
    cudaGetSymbolAddress((void**)&p_attn,g_attn_h);
    cudaGetSymbolAddress((void**)&p_hn2, g_hn2_h);
    cudaGetSymbolAddress((void**)&p_mid, g_mid_h);
    cudaGetSymbolAddress((void**)&p_zhi, g_zhi);
    cudaGetSymbolAddress((void**)&p_zlo, g_zlo);
    cudaGetSymbolAddress((void**)&p_wv,  g_wv_h);
    cudaGetSymbolAddress((void**)&p_wca, g_wca_h);
    cudaGetSymbolAddress((void**)&p_wcn, g_wcn_h);
    cudaGetSymbolAddress((void**)&p_wo,  g_wo_h);
    cudaGetSymbolAddress((void**)&p_w1,  g_w1_h);
    cudaGetSymbolAddress((void**)&p_w2,  g_w2_h);
    cudaGetSymbolAddress((void**)&p_z,   g_z_h);

    // smem: stages (half) vs fp32 C-tile, take max  (R14 values)
    constexpr int SM128 = ((3 * (128*40 + 32*136) * 2) > (128*132*4)) ? (3 * (128*40 + 32*136) * 2) : (128*132*4);
    constexpr int SM64  = ((3 * (64*40 + 32*72) * 2) > (64*68*4)) ? (3 * (64*40 + 32*72) * 2) : (64*68*4);
    cudaFuncSetAttribute(gemm_h<128,128,EPI_BIAS_F32>, cudaFuncAttributeMaxDynamicSharedMemorySize, SM128);
    cudaFuncSetAttribute(gemm_h<128,128,EPI_RES_F32 >, cudaFuncAttributeMaxDynamicSharedMemorySize, SM128);
    cudaFuncSetAttribute(gemm_h<128,128,EPI_GELU_H  >, cudaFuncAttributeMaxDynamicSharedMemorySize, SM128);
    cudaFuncSetAttribute(gemm_h<128,128,EPI_BIAS_H  >, cudaFuncAttributeMaxDynamicSharedMemorySize, SM128);
    cudaFuncSetAttribute(gemm_h< 64, 64,EPI_RES_F32 >, cudaFuncAttributeMaxDynamicSharedMemorySize, SM64);
    cudaFuncSetAttribute(attn_mma,                     cudaFuncAttributeMaxDynamicSharedMemorySize, AT_SMEM);

    auto cvt = [&](const float* src, __half* dst, int n) {
        int n4 = n / 4;
        f2h_kernel<<<(n4 + 255) / 256, 256>>>(src, dst, n4);
    };

    cvt(wv,  p_wv,  D_*D_);
    cvt(z,   p_z,   BS_*DC_);
    cvt(wca, p_wca, DC_*H_*HC_);
    ln1024<true><<<BS_, 256>>>(h, ln1g, ln1b, p_hn);
    // zh = z @ wca + bca  (fp32, for the Dekker split)
    gemm_h<128,128,EPI_BIAS_F32><<<dim3(2, BS_/128), 128, SM128>>>(p_z, p_wca, bca, nullptr, p_zh, BS_, 256, DC_);
    // value = fp16(hn @ wv + bv)
    gemm_h<128,128,EPI_BIAS_H><<<dim3(D_/128, BS_/128), 128, SM128>>>(p_hn, p_wv, bv, nullptr, p_val, BS_, D_, D_);
    cvt(wcn, p_wcn, D_*DC_);
    cvt(wo,  p_wo,  D_*D_);
    cvt(w1,  p_w1,  D_*MFF_);
    cvt(w2,  p_w2,  MFF_*D_);
    // Dekker split + norms
    score_prep<<<(BS_*H_ + 255) / 256, 256>>>(p_zh, p_zhi, p_zlo, p_zsq);
    // z_tmp = z + (hn @ wcn + bcn)
    gemm_h<64,64,EPI_RES_F32><<<dim3(1, BS_/64), 128, SM64>>>(p_hn, p_wcn, bcn, z, p_ztmp, BS_, DC_, D_);
    // fused flash attention (K/V prefetched one tile ahead)
    attn_mma<<<dim3(S_/128, BH_), 256, AT_SMEM>>>(p_zhi, p_zlo, p_zsq, gamma, p_val, p_attn);
    // h1 = h + (attn @ wo + bo)
    gemm_h<128,128,EPI_RES_F32><<<dim3(D_/128, BS_/128), 128, SM128>>>(p_attn, p_wo, bo, h, p_h1, BS_, D_, D_);
    // hn2 = fp16(LN2(h1))
    ln1024<true><<<BS_, 256>>>(p_h1, ln2g, ln2b, p_hn2);
    // mid = fp16(gelu(hn2 @ w1 + b1))
    gemm_h<128,128,EPI_GELU_H><<<dim3(MFF_/128, BS_/128), 128, SM128>>>(p_hn2, p_w1, b1, nullptr, p_mid, BS_, MFF_, D_);
    // out_h = h1 + (mid @ w2 + b2)
    gemm_h<128,128,EPI_RES_F32><<<dim3(D_/128, BS_/128), 128, SM128>>>(p_mid, p_w2, b2, p_h1, out_h, BS_, D_, MFF_);
    // out_z = LN_c(z_tmp)
    ln_small<<<BS_, 32>>>(p_ztmp, lncg, lncb, out_z, DC_);
}

// round 17
// speedup vs baseline: 1.5528x; 1.5528x over previous
#include <cuda_runtime.h>
#include <cuda_fp16.h>
#include <mma.h>
#include <math.h>

using namespace nvcuda;

#define B_   2
#define S_   2048
#define D_   1024
#define H_   16
#define DC_  64
#define HC_  16
#define MFF_ 4096
#define DH_  64
#define BS_  (B_*S_)      // 4096
#define BH_  (B_*H_)      // 32

// ---------------- scratch (static device globals; no allocation) ----------------
__device__ float  g_zh  [BS_*H_*HC_];
__device__ float  g_h1  [BS_*D_];
__device__ float  g_ztmp[BS_*DC_];
__device__ float  g_zsq [BS_*H_];
// half activations / operands
__device__ __half g_hn_h  [BS_*D_];
__device__ __half g_val_h [BS_*D_];
__device__ __half g_attn_h[BS_*D_];
__device__ __half g_hn2_h [BS_*D_];
__device__ __half g_mid_h [BS_*MFF_];
__device__ __half g_zhi   [BS_*H_*HC_];  // hi part of zh (Dekker split)
__device__ __half g_zlo   [BS_*H_*HC_];  // lo part
// half weight copies
__device__ __half g_wv_h [D_*D_];
__device__ __half g_wca_h[DC_*H_*HC_];
__device__ __half g_wcn_h[D_*DC_];
__device__ __half g_wo_h [D_*D_];
__device__ __half g_w1_h [D_*MFF_];
__device__ __half g_w2_h [MFF_*D_];
__device__ __half g_z_h  [BS_*DC_];

// exp(s) for s <= 0, FMA-pipe only (no MUFU). ~2.4e-6 max rel err.
__device__ __forceinline__ float fast_exp_neg(float s) {
    float y = fmaxf(s * 1.4426950408889634f, -126.0f);
    float z = y + 12582912.0f;
    float r = z - 12582912.0f;
    float f = y - r;
    int   iz = __float_as_int(z);
    float sc = __int_as_float((iz + (127 - 0x400000)) << 23);
    float p = 0.0013333558f;
    p = fmaf(p, f, 0.0096181291f);
    p = fmaf(p, f, 0.0555041087f);
    p = fmaf(p, f, 0.2402265070f);
    p = fmaf(p, f, 0.6931471806f);
    p = fmaf(p, f, 1.0f);
    return sc * p;
}

enum { EPI_BIAS_F32 = 0, EPI_RES_F32 = 1, EPI_GELU_H = 2, EPI_BIAS_H = 3 };

__device__ __forceinline__ void cp_async16(void* smem_dst, const void* gmem_src) {
    unsigned sa = (unsigned)__cvta_generic_to_shared(smem_dst);
    asm volatile("cp.async.cg.shared.global [%0], [%1], 16;\n" :: "r"(sa), "l"(gmem_src));
}
__device__ __forceinline__ void cp_commit() {
    asm volatile("cp.async.commit_group;\n" ::);
}

// ---------------- merged fp32 -> fp16 conversion over up to 7 segments ---------
// Segments given by element-4 counts (n4); blocks span the concatenated range.
struct CvtSeg { const float* src; __half* dst; int n4; };

__global__ void f2h_multi(const float* s0, __half* d0, int n0,
                          const float* s1, __half* d1, int n1,
                          const float* s2, __half* d2, int n2,
                          const float* s3, __half* d3, int n3,
                          const float* s4, __half* d4, int n4,
                          const float* s5, __half* d5, int n5,
                          const float* s6, __half* d6, int n6)
{
    int i = blockIdx.x * blockDim.x + threadIdx.x;
    const float* src; __half* dst; int off = i;
    if      (off < n0) { src = s0; dst = d0; }
    else if ((off -= n0) < n1) { src = s1; dst = d1; }
    else if ((off -= n1) < n2) { src = s2; dst = d2; }
    else if ((off -= n2) < n3) { src = s3; dst = d3; }
    else if ((off -= n3) < n4) { src = s4; dst = d4; }
    else if ((off -= n4) < n5) { src = s5; dst = d5; }
    else if ((off -= n5) < n6) { src = s6; dst = d6; }
    else return;
    float4 v = ((const float4*)src)[off];
    __half2* yp = (__half2*)dst;
    yp[2*off]   = __floats2half2_rn(v.x, v.y);
    yp[2*off+1] = __floats2half2_rn(v.z, v.w);
}

// ---------------- score prep: Dekker split zh -> (hi, lo) fp16 + per-head norms --
__global__ void score_prep(const float* __restrict__ zh, __half* __restrict__ hi,
                           __half* __restrict__ lo, float* __restrict__ zsq)
{
    int t = blockIdx.x * blockDim.x + threadIdx.x;
    if (t >= BS_ * H_) return;
    const float4* src = (const float4*)(zh + (size_t)t * 16);
    __half hb[16], lb[16];
    float s = 0.f;
#pragma unroll
    for (int q = 0; q < 4; q++) {
        float4 v = src[q];
        float vv[4] = {v.x, v.y, v.z, v.w};
#pragma unroll
        for (int j = 0; j < 4; j++) {
            float x = vv[j];
            __half hx = __float2half_rn(x);
            float  rx = x - __half2float(hx);
            hb[q*4+j] = hx;
            lb[q*4+j] = __float2half_rn(rx);
            s = fmaf(x, x, s);
        }
    }
    ((uint4*)(hi + (size_t)t * 16))[0] = ((uint4*)hb)[0];
    ((uint4*)(hi + (size_t)t * 16))[1] = ((uint4*)hb)[1];
    ((uint4*)(lo + (size_t)t * 16))[0] = ((uint4*)lb)[0];
    ((uint4*)(lo + (size_t)t * 16))[1] = ((uint4*)lb)[1];
    zsq[t] = s;
}

// ---------------- fused flash attention (all tensor-core) — R14 verified -------
#define AT_QH   0
#define AT_QL   6144
#define AT_KH   12288
#define AT_KL   18432
#define AT_QSQ  24576
#define AT_KSQ  25088
#define AT_C    25600
#define AT_PH   60416
#define AT_VS   95232
#define AT_SMEM 113664

__global__ void __launch_bounds__(256, 1) attn_mma(
    const __half* __restrict__ zhi, const __half* __restrict__ zlo,
    const float* __restrict__ zsq, const float* __restrict__ gamma,
    const __half* __restrict__ V, __half* __restrict__ O)
{
    constexpr int LDQ = 24;   // halves
    constexpr int LDC = 68;   // floats
    constexpr int LDP = 136;  // halves
    constexpr int LDV = 72;   // halves
    extern __shared__ __align__(16) char smraw[];
    __half* qh  = (__half*)(smraw + AT_QH);
    __half* ql  = (__half*)(smraw + AT_QL);
    __half* kh  = (__half*)(smraw + AT_KH);
    __half* kl  = (__half*)(smraw + AT_KL);
    float*  qsq = (float*)(smraw + AT_QSQ);
    float*  ksq = (float*)(smraw + AT_KSQ);
    float*  C   = (float*)(smraw + AT_C);
    __half* Ph  = (__half*)(smraw + AT_PH);
    __half* Vs  = (__half*)(smraw + AT_VS);

    const int tid = threadIdx.x;
    const int wid = tid >> 5;
    const int bh = blockIdx.y;
    const int b = bh >> 4, h = bh & 15;
    const int q0 = blockIdx.x * 128;

    const float gx = gamma[h];
    const float g = (gx > 20.f) ? gx : log1pf(__expf(gx));
    const __half* Vb = V + (size_t)b * S_ * D_ + h * DH_;

    {
        int r = tid >> 1, part = tid & 1;
        size_t go = ((size_t)(b * S_ + q0 + r)) * (H_ * HC_) + h * 16 + part * 8;
        *(uint4*)(qh + r * LDQ + part * 8) = *(const uint4*)(zhi + go);
        *(uint4*)(ql + r * LDQ + part * 8) = *(const uint4*)(zlo + go);
        if (part == 0) qsq[r] = zsq[(size_t)(b * S_ + q0 + r) * H_ + h];
    }
    __syncthreads();

    wmma::fragment<wmma::matrix_a, 16, 16, 16, __half, wmma::row_major> a_hi, a_lo;
    wmma::load_matrix_sync(a_hi, qh + (wid * 16) * LDQ, LDQ);
    wmma::load_matrix_sync(a_lo, ql + (wid * 16) * LDQ, LDQ);

    const int row = tid >> 1;
    const int c0  = (tid & 1) * 32;
    const float qs = qsq[row];
    float rs = 0.f;

    wmma::fragment<wmma::accumulator, 16, 16, 16, float> acc_o[4];
#pragma unroll
    for (int j = 0; j < 4; j++) wmma::fill_fragment(acc_o[j], 0.0f);

    for (int kt = 0; kt < 16; ++kt) {
        const int k0 = kt * 128;
        __syncthreads();
        {
            int r = tid >> 1, part = tid & 1;
            size_t go = ((size_t)(b * S_ + k0 + r)) * (H_ * HC_) + h * 16 + part * 8;
            *(uint4*)(kh + r * LDQ + part * 8) = *(const uint4*)(zhi + go);
            *(uint4*)(kl + r * LDQ + part * 8) = *(const uint4*)(zlo + go);
            if (part == 0) ksq[r] = zsq[(size_t)(b * S_ + k0 + r) * H_ + h];
        }
#pragma unroll
        for (int i = tid; i < 128 * 8; i += 256) {
            int r = i >> 3, c = (i & 7) * 8;
            cp_async16(Vs + r * LDV + c, Vb + (size_t)(k0 + r) * D_ + c);
        }
        cp_commit();
        __syncthreads();

        wmma::fragment<wmma::accumulator, 16, 16, 16, float> acc[8];
#pragma unroll
        for (int j = 0; j < 8; j++) wmma::fill_fragment(acc[j], 0.0f);
#pragma unroll
        for (int j = 0; j < 8; j++) {
            wmma::fragment<wmma::matrix_b, 16, 16, 16, __half, wmma::col_major> b_hi, b_lo;
            wmma::load_matrix_sync(b_hi, kh + (j * 16) * LDQ, LDQ);
            wmma::load_matrix_sync(b_lo, kl + (j * 16) * LDQ, LDQ);
            wmma::mma_sync(acc[j], a_hi, b_hi, acc[j]);
            wmma::mma_sync(acc[j], a_hi, b_lo, acc[j]);
            wmma::mma_sync(acc[j], a_lo, b_hi, acc[j]);
        }

#pragma unroll
        for (int hv = 0; hv < 2; ++hv) {
#pragma unroll
            for (int jj = 0; jj < 4; jj++)
                wmma::store_matrix_sync(C + (wid * 16) * LDC + jj * 16,
                                        acc[hv * 4 + jj], LDC, wmma::mem_row_major);
            __syncthreads();
            const float* Crow = C + row * LDC + c0;
            const float* ks   = ksq + hv * 64 + c0;
            __half hb[32];
#pragma unroll
            for (int i = 0; i < 32; i += 4) {
                float4 dv = *(const float4*)(Crow + i);
                float d0 = fmaxf(fmaf(-2.f, dv.x, qs + ks[i + 0]), 0.f);
                float d1 = fmaxf(fmaf(-2.f, dv.y, qs + ks[i + 1]), 0.f);
                float d2 = fmaxf(fmaf(-2.f, dv.z, qs + ks[i + 2]), 0.f);
                float d3 = fmaxf(fmaf(-2.f, dv.w, qs + ks[i + 3]), 0.f);
                float p0 = fast_exp_neg(-g * d0);
                float p1 = fast_exp_neg(-g * d1);
                float p2 = fast_exp_neg(-g * d2);
                float p3 = fast_exp_neg(-g * d3);
                rs += (p0 + p1) + (p2 + p3);
                *(__half2*)&hb[i]     = __floats2half2_rn(p0, p1);
                *(__half2*)&hb[i + 2] = __floats2half2_rn(p2, p3);
            }
            __half* Pp = Ph + (size_t)row * LDP + hv * 64 + c0;
#pragma unroll
            for (int i = 0; i < 4; i++) ((uint4*)Pp)[i] = ((uint4*)hb)[i];
            __syncthreads();
        }

        asm volatile("cp.async.wait_group 0;\n" ::);
        __syncthreads();
#pragma unroll
        for (int kk = 0; kk < 128; kk += 16) {
            wmma::fragment<wmma::matrix_a, 16, 16, 16, __half, wmma::row_major> af;
            wmma::load_matrix_sync(af, Ph + (wid * 16) * LDP + kk, LDP);
#pragma unroll
            for (int j = 0; j < 4; j++) {
                wmma::fragment<wmma::matrix_b, 16, 16, 16, __half, wmma::row_major> bf;
                wmma::load_matrix_sync(bf, Vs + kk * LDV + j * 16, LDV);
                wmma::mma_sync(acc_o[j], af, bf, acc_o[j]);
            }
        }
    }

    rs += __shfl_xor_sync(0xffffffffu, rs, 1);
    if ((tid & 1) == 0) qsq[row] = 1.0f / rs;   // qsq reused as linv
#pragma unroll
    for (int j = 0; j < 4; j++)
        wmma::store_matrix_sync(C + (wid * 16) * LDC + j * 16, acc_o[j], LDC, wmma::mem_row_major);
    __syncthreads();

#pragma unroll 4
    for (int i = tid; i < 128 * 16; i += 256) {
        int r = i >> 4, c = (i & 15) * 4;
        float4 v = *(float4*)&C[r * LDC + c];
        float li = qsq[r];
        v.x *= li; v.y *= li; v.z *= li; v.w *= li;
        __half2* yp = (__half2*)(O + ((size_t)(b * S_ + q0 + r)) * D_ + h * DH_ + c);
        yp[0] = __floats2half2_rn(v.x, v.y);
        yp[1] = __floats2half2_rn(v.z, v.w);
    }
}

// ---------------- pipelined fp16 GEMM (R14-verified: BK=32, 3 stages) ----------
template<int BM, int BN, int EPI>
__global__ void __launch_bounds__(128, 2) gemm_h(
    const __half* __restrict__ A, const __half* __restrict__ Bw,
    const float* __restrict__ bias, const float* __restrict__ Rres,
    void* __restrict__ Cout, int Mdim, int Ndim, int Kdim)
{
    constexpr int BK = 32;
    constexpr int STAGES = 3;
    constexpr int LDA = BK + 8;
    constexpr int LDB = BN + 8;
    constexpr int LDC = BN + 4;
    constexpr int WTM = BM / 2;
    constexpr int WTN = BN / 2;
    constexpr int FM  = WTM / 16;
    constexpr int FN  = WTN / 16;
    constexpr int A_STG = BM * LDA;
    constexpr int B_STG = BK * LDB;
    constexpr int CHB = BN / 8;

    extern __shared__ __align__(16) char smraw[];
    __half* As = (__half*)smraw;
    __half* Bs = As + STAGES * A_STG;

    const int tid = threadIdx.x;
    const int wid = tid >> 5;
    const int wm = wid >> 1, wn = wid & 1;
    const int bm0 = blockIdx.y * BM, bn0 = blockIdx.x * BN;

    wmma::fragment<wmma::accumulator, 16, 16, 16, float> acc[FM][FN];
#pragma unroll
    for (int i = 0; i < FM; i++)
#pragma unroll
        for (int j = 0; j < FN; j++) wmma::fill_fragment(acc[i][j], 0.0f);

    auto load_tile = [&](int stage, int k0) {
        __half* Ad = As + stage * A_STG;
        __half* Bd = Bs + stage * B_STG;
#pragma unroll
        for (int i = tid; i < BM * 4; i += 128) {
            int r = i >> 2, c = (i & 3) * 8;
            cp_async16(Ad + r * LDA + c, A + (size_t)(bm0 + r) * Kdim + k0 + c);
        }
#pragma unroll
        for (int i = tid; i < BK * CHB; i += 128) {
            int r = i / CHB, c = (i % CHB) * 8;
            cp_async16(Bd + r * LDB + c, Bw + (size_t)(k0 + r) * Ndim + bn0 + c);
        }
    };

    const int KT = Kdim / BK;
#pragma unroll
    for (int s = 0; s < STAGES - 1; ++s) {
        if (s < KT) load_tile(s, s * BK);
        cp_commit();
    }

    int read = 0, write = STAGES - 1;
    for (int it = 0; it < KT; ++it) {
        asm volatile("cp.async.wait_group %0;\n" :: "n"(STAGES - 2));
        __syncthreads();
        int knext = (it + STAGES - 1) * BK;
        if (knext < Kdim) load_tile(write, knext);
        cp_commit();

        const __half* Asr = As + read * A_STG;
        const __half* Bsr = Bs + read * B_STG;
#pragma unroll
        for (int kk = 0; kk < BK; kk += 16) {
            wmma::fragment<wmma::matrix_a, 16, 16, 16, __half, wmma::row_major> af[FM];
            wmma::fragment<wmma::matrix_b, 16, 16, 16, __half, wmma::row_major> bf[FN];
#pragma unroll
            for (int i = 0; i < FM; i++)
                wmma::load_matrix_sync(af[i], Asr + (wm * WTM + i * 16) * LDA + kk, LDA);
#pragma unroll
            for (int j = 0; j < FN; j++)
                wmma::load_matrix_sync(bf[j], Bsr + kk * LDB + wn * WTN + j * 16, LDB);
#pragma unroll
            for (int i = 0; i < FM; i++)
#pragma unroll
                for (int j = 0; j < FN; j++)
                    wmma::mma_sync(acc[i][j], af[i], bf[j], acc[i][j]);
        }
        read = (read + 1) % STAGES;
        write = (write + 1) % STAGES;
    }

    asm volatile("cp.async.wait_group 0;\n" ::);
    __syncthreads();

    float* Cs = (float*)smraw;
#pragma unroll
    for (int i = 0; i < FM; i++)
#pragma unroll
        for (int j = 0; j < FN; j++)
            wmma::store_matrix_sync(Cs + (wm * WTM + i * 16) * LDC + wn * WTN + j * 16,
                                    acc[i][j], LDC, wmma::mem_row_major);
    __syncthreads();

#pragma unroll 4
    for (int i = tid; i < BM * (BN / 4); i += 128) {
        int r = i / (BN / 4), c = (i % (BN / 4)) * 4;
        float4 v = *(float4*)&Cs[r * LDC + c];
        float4 bb = *(const float4*)(bias + bn0 + c);
        v.x += bb.x; v.y += bb.y; v.z += bb.z; v.w += bb.w;
        size_t off = (size_t)(bm0 + r) * Ndim + bn0 + c;
        if (EPI == EPI_BIAS_F32) {
            *(float4*)((float*)Cout + off) = v;
        } else if (EPI == EPI_RES_F32) {
            float4 rr = *(const float4*)(Rres + off);
            v.x += rr.x; v.y += rr.y; v.z += rr.z; v.w += rr.w;
            *(float4*)((float*)Cout + off) = v;
        } else if (EPI == EPI_GELU_H) {
            v.x = 0.5f * v.x * (1.0f + erff(v.x * 0.70710678118654752f));
            v.y = 0.5f * v.y * (1.0f + erff(v.y * 0.70710678118654752f));
            v.z = 0.5f * v.z * (1.0f + erff(v.z * 0.70710678118654752f));
            v.w = 0.5f * v.w * (1.0f + erff(v.w * 0.70710678118654752f));
            __half2* yp = (__half2*)((__half*)Cout + off);
            yp[0] = __floats2half2_rn(v.x, v.y);
            yp[1] = __floats2half2_rn(v.z, v.w);
        } else {
            __half2* yp = (__half2*)((__half*)Cout + off);
            yp[0] = __floats2half2_rn(v.x, v.y);
            yp[1] = __floats2half2_rn(v.z, v.w);
        }
    }
}

// ---------------- LayerNorm D=1024, vectorized (fp32 or fp16 output) -----------
template<bool HOUT>
__global__ void ln1024(const float* __restrict__ x, const float* __restrict__ gm,
                       const float* __restrict__ bt, void* __restrict__ y)
{
    const int row = blockIdx.x;
    const int tid = threadIdx.x;
    float4 v = ((const float4*)x)[(size_t)row * 256 + tid];
    float s  = (v.x + v.y) + (v.z + v.w);
    float s2 = fmaf(v.x, v.x, fmaf(v.y, v.y, fmaf(v.z, v.z, v.w * v.w)));
    __shared__ float red[2][8];
    const int lane = tid & 31, wid = tid >> 5;
#pragma unroll
    for (int off = 16; off; off >>= 1) {
        s  += __shfl_xor_sync(0xffffffffu, s, off);
        s2 += __shfl_xor_sync(0xffffffffu, s2, off);
    }
    if (lane == 0) { red[0][wid] = s; red[1][wid] = s2; }
    __syncthreads();
    if (wid == 0) {
        s  = (lane < 8) ? red[0][lane] : 0.f;
        s2 = (lane < 8) ? red[1][lane] : 0.f;
#pragma unroll
        for (int off = 4; off; off >>= 1) {
            s  += __shfl_xor_sync(0xffffffffu, s, off);
            s2 += __shfl_xor_sync(0xffffffffu, s2, off);
        }
        if (lane == 0) { red[0][0] = s; red[1][0] = s2; }
    }
    __syncthreads();
    s = red[0][0]; s2 = red[1][0];
    const float mean = s * (1.0f / 1024.0f);
    const float var  = s2 * (1.0f / 1024.0f) - mean * mean;
    const float inv  = rsqrtf(var + 1e-5f);
    float4 g4 = ((const float4*)gm)[tid];
    float4 b4 = ((const float4*)bt)[tid];
    float4 o;
    o.x = (v.x - mean) * inv * g4.x + b4.x;
    o.y = (v.y - mean) * inv * g4.y + b4.y;
    o.z = (v.z - mean) * inv * g4.z + b4.z;
    o.w = (v.w - mean) * inv * g4.w + b4.w;
    if (HOUT) {
        __half2* yp = (__half2*)((__half*)y + (size_t)row * 1024 + tid * 4);
        yp[0] = __floats2half2_rn(o.x, o.y);
        yp[1] = __floats2half2_rn(o.z, o.w);
    } else {
        ((float4*)y)[(size_t)row * 256 + tid] = o;
    }
}

// ---------------- generic LayerNorm (small Dd) ----------------
__global__ void ln_small(const float* __restrict__ x, const float* __restrict__ gm,
                         const float* __restrict__ bt, float* __restrict__ y, int Dd)
{
    const int row = blockIdx.x;
    const float* xr = x + (size_t)row * Dd;
    float s = 0.f, s2 = 0.f;
    for (int i = threadIdx.x; i < Dd; i += blockDim.x) {
        float v = xr[i]; s += v; s2 = fmaf(v, v, s2);
    }
#pragma unroll
    for (int off = 16; off; off >>= 1) {
        s  += __shfl_xor_sync(0xffffffffu, s, off);
        s2 += __shfl_xor_sync(0xffffffffu, s2, off);
    }
    s  = __shfl_sync(0xffffffffu, s, 0);
    s2 = __shfl_sync(0xffffffffu, s2, 0);
    const float mean = s / Dd;
    const float var  = s2 / Dd - mean * mean;
    const float inv  = rsqrtf(var + 1e-5f);
    float* yr = y + (size_t)row * Dd;
    for (int i = threadIdx.x; i < Dd; i += blockDim.x)
        yr[i] = (xr[i] - mean) * inv * gm[i] + bt[i];
}

// ---------------- launch ----------------
extern "C" void kernel_launch(void* const* d_in, const int* in_sizes, int n_in,
                              void* d_out, int out_size)
{
    const float* h    = (const float*)d_in[0];
    const float* z    = (const float*)d_in[1];
    const float* wv   = (const float*)d_in[2];
    const float* bv   = (const float*)d_in[3];
    const float* wca  = (const float*)d_in[4];
    const float* bca  = (const float*)d_in[5];
    const float* wcn  = (const float*)d_in[6];
    const float* bcn  = (const float*)d_in[7];
    const float* wo   = (const float*)d_in[8];
    const float* bo   = (const float*)d_in[9];
    const float* gamma= (const float*)d_in[10];
    const float* w1   = (const float*)d_in[11];
    const float* b1   = (const float*)d_in[12];
    const float* w2   = (const float*)d_in[13];
    const float* b2   = (const float*)d_in[14];
    const float* ln1g = (const float*)d_in[15];
    const float* ln1b = (const float*)d_in[16];
    const float* ln2g = (const float*)d_in[17];
    const float* ln2b = (const float*)d_in[18];
    const float* lncg = (const float*)d_in[19];
    const float* lncb = (const float*)d_in[20];

    float* out_h = (float*)d_out;
    float* out_z = out_h + (size_t)BS_ * D_;

    float  *p_zh, *p_h1, *p_ztmp, *p_zsq;
    __half *p_hn, *p_val, *p_attn, *p_hn2, *p_mid, *p_zhi, *p_zlo;
    __half *p_wv, *p_wca, *p_wcn, *p_wo, *p_w1, *p_w2, *p_z;
    cudaGetSymbolAddress((void**)&p_zh,  g_zh);
    cudaGetSymbolAddress((void**)&p_h1,  g_h1);
    cudaGetSymbolAddress((void**)&p_ztmp,g_ztmp);
    cudaGetSymbolAddress((void**)&p_zsq, g_zsq);
    cudaGetSymbolAddress((void**)&p_hn,  g_hn_h);
    cudaGetSymbolAddress((void**)&p_val, g_val_h);
    cudaGetSymbolAddress((void**)&p_attn,g_attn_h);
    cudaGetSymbolAddress((void**)&p_hn2, g_hn2_h);
    cudaGetSymbolAddress((void**)&p_mid, g_mid_h);
    cudaGetSymbolAddress((void**)&p_zhi, g_zhi);
    cudaGetSymbolAddress((void**)&p_zlo, g_zlo);
    cudaGetSymbolAddress((void**)&p_wv,  g_wv_h);
    cudaGetSymbolAddress((void**)&p_wca, g_wca_h);
    cudaGetSymbolAddress((void**)&p_wcn, g_wcn_h);
    cudaGetSymbolAddress((void**)&p_wo,  g_wo_h);
    cudaGetSymbolAddress((void**)&p_w1,  g_w1_h);
    cudaGetSymbolAddress((void**)&p_w2,  g_w2_h);
    cudaGetSymbolAddress((void**)&p_z,   g_z_h);

    // smem: stages (half) vs fp32 C-tile, take max  (R14 values)
    constexpr int SM128 = ((3 * (128*40 + 32*136) * 2) > (128*132*4)) ? (3 * (128*40 + 32*136) * 2) : (128*132*4);
    constexpr int SM64  = ((3 * (64*40 + 32*72) * 2) > (64*68*4)) ? (3 * (64*40 + 32*72) * 2) : (64*68*4);
    cudaFuncSetAttribute(gemm_h<128,128,EPI_BIAS_F32>, cudaFuncAttributeMaxDynamicSharedMemorySize, SM128);
    cudaFuncSetAttribute(gemm_h<128,128,EPI_RES_F32 >, cudaFuncAttributeMaxDynamicSharedMemorySize, SM128);
    cudaFuncSetAttribute(gemm_h<128,128,EPI_GELU_H  >, cudaFuncAttributeMaxDynamicSharedMemorySize, SM128);
    cudaFuncSetAttribute(gemm_h<128,128,EPI_BIAS_H  >, cudaFuncAttributeMaxDynamicSharedMemorySize, SM128);
    cudaFuncSetAttribute(gemm_h< 64, 64,EPI_RES_F32 >, cudaFuncAttributeMaxDynamicSharedMemorySize, SM64);
    cudaFuncSetAttribute(attn_mma,                     cudaFuncAttributeMaxDynamicSharedMemorySize, AT_SMEM);

    // all fp32->fp16 conversions in ONE launch (weights + z)
    {
        int n0 = (D_*D_)/4, n1 = (BS_*DC_)/4, n2 = (DC_*H_*HC_)/4, n3 = (D_*DC_)/4;
        int n4 = (D_*D_)/4, n5 = (D_*MFF_)/4, n6 = (MFF_*D_)/4;
        int total = n0 + n1 + n2 + n3 + n4 + n5 + n6;
        f2h_multi<<<(total + 255) / 256, 256>>>(
            wv, p_wv, n0,  z, p_z, n1,  wca, p_wca, n2,  wcn, p_wcn, n3,
            wo, p_wo, n4,  w1, p_w1, n5,  w2, p_w2, n6);
    }
    ln1024<true><<<BS_, 256>>>(h, ln1g, ln1b, p_hn);
    // zh = z @ wca + bca  (fp32, for the Dekker split)
    gemm_h<128,128,EPI_BIAS_F32><<<dim3(2, BS_/128), 128, SM128>>>(p_z, p_wca, bca, nullptr, p_zh, BS_, 256, DC_);
    // value = fp16(hn @ wv + bv)
    gemm_h<128,128,EPI_BIAS_H><<<dim3(D_/128, BS_/128), 128, SM128>>>(p_hn, p_wv, bv, nullptr, p_val, BS_, D_, D_);
    // Dekker split + norms
    score_prep<<<(BS_*H_ + 255) / 256, 256>>>(p_zh, p_zhi, p_zlo, p_zsq);
    // z_tmp = z + (hn @ wcn + bcn)
    gemm_h<64,64,EPI_RES_F32><<<dim3(1, BS_/64), 128, SM64>>>(p_hn, p_wcn, bcn, z, p_ztmp, BS_, DC_, D_);
    // fused flash attention
    attn_mma<<<dim3(S_/128, BH_), 256, AT_SMEM>>>(p_zhi, p_zlo, p_zsq, gamma, p_val, p_attn);
    // h1 = h + (attn @ wo + bo)
    gemm_h<128,128,EPI_RES_F32><<<dim3(D_/128, BS_/128), 128, SM128>>>(p_attn, p_wo, bo, h, p_h1, BS_, D_, D_);
    // hn2 = fp16(LN2(h1))
    ln1024<true><<<BS_, 256>>>(p_h1, ln2g, ln2b, p_hn2);
    // mid = fp16(gelu(hn2 @ w1 + b1))
    gemm_h<128,128,EPI_GELU_H><<<dim3(MFF_/128, BS_/128), 128, SM128>>>(p_hn2, p_w1, b1, nullptr, p_mid, BS_, MFF_, D_);
    // out_h = h1 + (mid @ w2 + b2)
    gemm_h<128,128,EPI_RES_F32><<<dim3(D_/128, BS_/128), 128, SM128>>>(p_mid, p_w2, b2, p_h1, out_h, BS_, D_, MFF_);
    // out_z = LN_c(z_tmp)
    ln_small<<<BS_, 32>>>(p_ztmp, lncg, lncb, out_z, DC_);
}